// round 1
// baseline (speedup 1.0000x reference)
#include <cuda_runtime.h>

#define LEAK 0.2f
constexpr int B_  = 2;
constexpr int C_  = 16;
constexpr int VOL = 96 * 96 * 96;
constexpr int DVF = 48;

// Scratch (declared as device globals per harness rules).
// g_warped: warped source [B,16,VOL]; reused afterwards as f [B,16,VOL]
// g_corr:   cost volume   [B,27,VOL]; reused afterwards as fsum [B,16,VOL]
__device__ float g_warped[(size_t)B_ * C_ * VOL];
__device__ float g_corr[(size_t)B_ * 27 * VOL];

__device__ __forceinline__ float lrelu(float v) { return v > 0.f ? v : LEAK * v; }

// ---------------------------------------------------------------------------
// K1: trilinear upsample of dvf (48^3 -> 96^3, align_corners) + warp source
// ---------------------------------------------------------------------------
__global__ void warp_kernel(const float* __restrict__ src,
                            const float* __restrict__ dvf)
{
    int idx = blockIdx.x * blockDim.x + threadIdx.x;
    if (idx >= B_ * VOL) return;
    int b = idx / VOL;
    int r = idx - b * VOL;
    int z = r / (96 * 96);
    int y = (r / 96) % 96;
    int x = r % 96;

    // align_corners resize position
    const float sc = 47.0f / 95.0f;
    float pz = z * sc, py = y * sc, px = x * sc;
    int z0 = (int)pz, y0 = (int)py, x0 = (int)px;
    int z1 = min(z0 + 1, DVF - 1), y1 = min(y0 + 1, DVF - 1), x1 = min(x0 + 1, DVF - 1);
    float wz = pz - (float)z0, wy = py - (float)y0, wx = px - (float)x0;

    const float* dv = dvf + (size_t)b * 3 * DVF * DVF * DVF;
    float flow[3];
#pragma unroll
    for (int cc = 0; cc < 3; cc++) {
        const float* p = dv + (size_t)cc * DVF * DVF * DVF;
        float v000 = __ldg(p + (z0 * 48 + y0) * 48 + x0);
        float v001 = __ldg(p + (z0 * 48 + y0) * 48 + x1);
        float v010 = __ldg(p + (z0 * 48 + y1) * 48 + x0);
        float v011 = __ldg(p + (z0 * 48 + y1) * 48 + x1);
        float v100 = __ldg(p + (z1 * 48 + y0) * 48 + x0);
        float v101 = __ldg(p + (z1 * 48 + y0) * 48 + x1);
        float v110 = __ldg(p + (z1 * 48 + y1) * 48 + x0);
        float v111 = __ldg(p + (z1 * 48 + y1) * 48 + x1);
        float v00 = v000 * (1.f - wx) + v001 * wx;
        float v01 = v010 * (1.f - wx) + v011 * wx;
        float v10 = v100 * (1.f - wx) + v101 * wx;
        float v11 = v110 * (1.f - wx) + v111 * wx;
        float v0 = v00 * (1.f - wy) + v01 * wy;
        float v1 = v10 * (1.f - wy) + v11 * wy;
        flow[cc] = v0 * (1.f - wz) + v1 * wz;
    }

    float zc = (float)z + flow[0];
    float yc = (float)y + flow[1];
    float xc = (float)x + flow[2];
    float zf = floorf(zc), yf = floorf(yc), xf = floorf(xc);
    float fz = zc - zf, fy = yc - yf, fx = xc - xf;
    int iz0 = (int)zf, iy0 = (int)yf, ix0 = (int)xf;

    int   zi[2] = { iz0, iz0 + 1 };
    int   yi[2] = { iy0, iy0 + 1 };
    int   xi[2] = { ix0, ix0 + 1 };
    float wzv[2] = { 1.f - fz, fz };
    float wyv[2] = { 1.f - fy, fy };
    float wxv[2] = { 1.f - fx, fx };

    int   idx8[8];
    float w8[8];
    int j = 0;
#pragma unroll
    for (int a = 0; a < 2; a++)
#pragma unroll
        for (int bb = 0; bb < 2; bb++)
#pragma unroll
            for (int c2 = 0; c2 < 2; c2++) {
                int zz = zi[a], yy = yi[bb], xx = xi[c2];
                bool valid = (zz >= 0 && zz < 96 && yy >= 0 && yy < 96 &&
                              xx >= 0 && xx < 96);
                int zcl = min(max(zz, 0), 95);
                int ycl = min(max(yy, 0), 95);
                int xcl = min(max(xx, 0), 95);
                idx8[j] = (zcl * 96 + ycl) * 96 + xcl;
                w8[j] = valid ? (wzv[a] * wyv[bb] * wxv[c2]) : 0.f;
                j++;
            }

    const float* sb = src + (size_t)b * C_ * VOL;
    float* ob = g_warped + (size_t)b * C_ * VOL + r;
#pragma unroll
    for (int c = 0; c < C_; c++) {
        const float* sp = sb + (size_t)c * VOL;
        float v = 0.f;
#pragma unroll
        for (int k = 0; k < 8; k++) v = fmaf(w8[k], __ldg(sp + idx8[k]), v);
        ob[(size_t)c * VOL] = v;
    }
}

// ---------------------------------------------------------------------------
// K2: 27-shift cost volume: corr[s] = lrelu(mean_c target[c] * warped_shift[c])
// ---------------------------------------------------------------------------
__global__ void corr_kernel(const float* __restrict__ tgt)
{
    int idx = blockIdx.x * blockDim.x + threadIdx.x;
    if (idx >= B_ * VOL) return;
    int b = idx / VOL;
    int r = idx - b * VOL;
    int z = r / (96 * 96);
    int y = (r / 96) % 96;
    int x = r % 96;

    float t[C_];
    const float* tp = tgt + (size_t)b * C_ * VOL + r;
#pragma unroll
    for (int c = 0; c < C_; c++) t[c] = __ldg(tp + (size_t)c * VOL);

    const float* wp = g_warped + (size_t)b * C_ * VOL;
    float* op = g_corr + (size_t)b * 27 * VOL + r;

    int s = 0;
#pragma unroll
    for (int dz = -1; dz <= 1; dz++) {
        int zz = z + dz;
#pragma unroll
        for (int dy = -1; dy <= 1; dy++) {
            int yy = y + dy;
#pragma unroll
            for (int dx = -1; dx <= 1; dx++) {
                int xx = x + dx;
                float acc = 0.f;
                if (zz >= 0 && zz < 96 && yy >= 0 && yy < 96 && xx >= 0 && xx < 96) {
                    const float* q = wp + ((zz * 96 + yy) * 96 + xx);
#pragma unroll
                    for (int c = 0; c < C_; c++)
                        acc = fmaf(t[c], __ldg(q + (size_t)c * VOL), acc);
                }
                op[(size_t)s * VOL] = lrelu(acc * 0.0625f);
                s++;
            }
        }
    }
}

// ---------------------------------------------------------------------------
// K3: conv1  (in = concat(source[16], corr[27], target[16]) = 59ch -> 16ch)
// weights staged in smem as [ci][k][co] for broadcast reads
// ---------------------------------------------------------------------------
__global__ void conv1_kernel(const float* __restrict__ src,
                             const float* __restrict__ tgt,
                             const float* __restrict__ w,
                             const float* __restrict__ bias)
{
    constexpr int CIN = 59, COUT = 16;
    extern __shared__ float sw[];
    int tid = threadIdx.y * blockDim.x + threadIdx.x;
    int nth = blockDim.x * blockDim.y;
    for (int i = tid; i < CIN * 27 * COUT; i += nth) {
        int co = i % COUT;
        int rest = i / COUT;
        int k = rest % 27;
        int ci = rest / 27;
        sw[i] = __ldg(w + (co * CIN + ci) * 27 + k);
    }
    __syncthreads();

    int x = blockIdx.x * 32 + threadIdx.x;
    int y = blockIdx.y * 8 + threadIdx.y;
    int bz = blockIdx.z;
    int b = bz >> 2;
    int zbase = (bz & 3) * 24;

    const float* corr = g_corr + (size_t)b * 27 * VOL;
    const float* sb = src + (size_t)b * C_ * VOL;
    const float* tb = tgt + (size_t)b * C_ * VOL;
    float* outp = g_warped + (size_t)b * C_ * VOL;   // f overwrites warped

    for (int z = zbase; z < zbase + 24; z++) {
        float acc[COUT];
#pragma unroll
        for (int co = 0; co < COUT; co++) acc[co] = __ldg(bias + co);
        bool interior = (x >= 1 && x < 95 && y >= 1 && y < 95 && z >= 1 && z < 95);
        int center = (z * 96 + y) * 96 + x;

        for (int ci = 0; ci < CIN; ci++) {
            const float* base;
            if (ci < 16)      base = sb + (size_t)ci * VOL;
            else if (ci < 43) base = corr + (size_t)(ci - 16) * VOL;
            else              base = tb + (size_t)(ci - 43) * VOL;
            const float* swc = sw + ci * 27 * COUT;

            if (interior) {
                const float* p0 = base + center - (96 * 96 + 96 + 1);
#pragma unroll
                for (int kz = 0; kz < 3; kz++) {
#pragma unroll
                    for (int ky = 0; ky < 3; ky++) {
                        const float* p = p0 + (kz * 96 + ky) * 96;
                        float v0 = __ldg(p), v1 = __ldg(p + 1), v2 = __ldg(p + 2);
                        const float* wk = swc + (kz * 3 + ky) * 3 * COUT;
#pragma unroll
                        for (int co = 0; co < COUT; co++) acc[co] = fmaf(v0, wk[co], acc[co]);
#pragma unroll
                        for (int co = 0; co < COUT; co++) acc[co] = fmaf(v1, wk[COUT + co], acc[co]);
#pragma unroll
                        for (int co = 0; co < COUT; co++) acc[co] = fmaf(v2, wk[2 * COUT + co], acc[co]);
                    }
                }
            } else {
                for (int kz = 0; kz < 3; kz++) {
                    int zz = z + kz - 1;
                    if (zz < 0 || zz > 95) continue;
                    for (int ky = 0; ky < 3; ky++) {
                        int yy = y + ky - 1;
                        if (yy < 0 || yy > 95) continue;
                        const float* p = base + (zz * 96 + yy) * 96 + x;
                        const float* wk = swc + (kz * 3 + ky) * 3 * COUT;
                        if (x >= 1) {
                            float v = __ldg(p - 1);
#pragma unroll
                            for (int co = 0; co < COUT; co++) acc[co] = fmaf(v, wk[co], acc[co]);
                        }
                        {
                            float v = __ldg(p);
#pragma unroll
                            for (int co = 0; co < COUT; co++) acc[co] = fmaf(v, wk[COUT + co], acc[co]);
                        }
                        if (x < 95) {
                            float v = __ldg(p + 1);
#pragma unroll
                            for (int co = 0; co < COUT; co++) acc[co] = fmaf(v, wk[2 * COUT + co], acc[co]);
                        }
                    }
                }
            }
        }
#pragma unroll
        for (int co = 0; co < COUT; co++)
            outp[(size_t)co * VOL + center] = lrelu(acc[co]);
    }
}

// ---------------------------------------------------------------------------
// Generic 3x3x3 conv: CIN -> COUT, lrelu; optional residual (out = in + lrelu)
// ---------------------------------------------------------------------------
template <int CIN, int COUT, bool RES>
__global__ void convg_kernel(const float* __restrict__ in,
                             const float* __restrict__ w,
                             const float* __restrict__ bias,
                             float* __restrict__ out)
{
    extern __shared__ float sw[];
    int tid = threadIdx.y * blockDim.x + threadIdx.x;
    int nth = blockDim.x * blockDim.y;
    for (int i = tid; i < CIN * 27 * COUT; i += nth) {
        int co = i % COUT;
        int rest = i / COUT;
        int k = rest % 27;
        int ci = rest / 27;
        sw[i] = __ldg(w + (co * CIN + ci) * 27 + k);
    }
    __syncthreads();

    int x = blockIdx.x * 32 + threadIdx.x;
    int y = blockIdx.y * 8 + threadIdx.y;
    int bz = blockIdx.z;
    int b = bz >> 2;
    int zbase = (bz & 3) * 24;

    const float* ib = in + (size_t)b * CIN * VOL;
    float* ob = out + (size_t)b * COUT * VOL;

    for (int z = zbase; z < zbase + 24; z++) {
        float acc[COUT];
#pragma unroll
        for (int co = 0; co < COUT; co++) acc[co] = __ldg(bias + co);
        bool interior = (x >= 1 && x < 95 && y >= 1 && y < 95 && z >= 1 && z < 95);
        int center = (z * 96 + y) * 96 + x;

        for (int ci = 0; ci < CIN; ci++) {
            const float* base = ib + (size_t)ci * VOL;
            const float* swc = sw + ci * 27 * COUT;
            if (interior) {
                const float* p0 = base + center - (96 * 96 + 96 + 1);
#pragma unroll
                for (int kz = 0; kz < 3; kz++) {
#pragma unroll
                    for (int ky = 0; ky < 3; ky++) {
                        const float* p = p0 + (kz * 96 + ky) * 96;
                        float v0 = __ldg(p), v1 = __ldg(p + 1), v2 = __ldg(p + 2);
                        const float* wk = swc + (kz * 3 + ky) * 3 * COUT;
#pragma unroll
                        for (int co = 0; co < COUT; co++) acc[co] = fmaf(v0, wk[co], acc[co]);
#pragma unroll
                        for (int co = 0; co < COUT; co++) acc[co] = fmaf(v1, wk[COUT + co], acc[co]);
#pragma unroll
                        for (int co = 0; co < COUT; co++) acc[co] = fmaf(v2, wk[2 * COUT + co], acc[co]);
                    }
                }
            } else {
                for (int kz = 0; kz < 3; kz++) {
                    int zz = z + kz - 1;
                    if (zz < 0 || zz > 95) continue;
                    for (int ky = 0; ky < 3; ky++) {
                        int yy = y + ky - 1;
                        if (yy < 0 || yy > 95) continue;
                        const float* p = base + (zz * 96 + yy) * 96 + x;
                        const float* wk = swc + (kz * 3 + ky) * 3 * COUT;
                        if (x >= 1) {
                            float v = __ldg(p - 1);
#pragma unroll
                            for (int co = 0; co < COUT; co++) acc[co] = fmaf(v, wk[co], acc[co]);
                        }
                        {
                            float v = __ldg(p);
#pragma unroll
                            for (int co = 0; co < COUT; co++) acc[co] = fmaf(v, wk[COUT + co], acc[co]);
                        }
                        if (x < 95) {
                            float v = __ldg(p + 1);
#pragma unroll
                            for (int co = 0; co < COUT; co++) acc[co] = fmaf(v, wk[2 * COUT + co], acc[co]);
                        }
                    }
                }
            }
        }
#pragma unroll
        for (int co = 0; co < COUT; co++) {
            float v = lrelu(acc[co]);
            if (RES) v += __ldg(ib + (size_t)co * VOL + center);
            ob[(size_t)co * VOL + center] = v;
        }
    }
}

// ---------------------------------------------------------------------------
extern "C" void kernel_launch(void* const* d_in, const int* in_sizes, int n_in,
                              void* d_out, int out_size)
{
    const float* src = (const float*)d_in[0];
    const float* tgt = (const float*)d_in[1];
    const float* dvf = (const float*)d_in[2];
    const float* w1  = (const float*)d_in[3];
    const float* b1  = (const float*)d_in[4];
    const float* w2  = (const float*)d_in[5];
    const float* b2  = (const float*)d_in[6];
    const float* w3  = (const float*)d_in[7];
    const float* b3  = (const float*)d_in[8];
    float* out = (float*)d_out;

    const int smem1 = 59 * 27 * 16 * (int)sizeof(float);   // ~100 KB
    cudaFuncSetAttribute(conv1_kernel, cudaFuncAttributeMaxDynamicSharedMemorySize, smem1);

    float* fptr = nullptr;   // g_warped (reused as f)
    float* fsum = nullptr;   // g_corr (reused as f + f1)
    cudaGetSymbolAddress((void**)&fptr, g_warped);
    cudaGetSymbolAddress((void**)&fsum, g_corr);

    int nvox = B_ * VOL;
    warp_kernel<<<(nvox + 255) / 256, 256>>>(src, dvf);
    corr_kernel<<<(nvox + 255) / 256, 256>>>(tgt);

    dim3 blk(32, 8, 1);
    dim3 grd(3, 12, B_ * 4);
    conv1_kernel<<<grd, blk, smem1>>>(src, tgt, w1, b1);
    convg_kernel<16, 16, true><<<grd, blk, 16 * 27 * 16 * sizeof(float)>>>(fptr, w2, b2, fsum);
    convg_kernel<16, 3, false><<<grd, blk, 16 * 27 * 3 * sizeof(float)>>>(fsum, w3, b3, out);
}

// round 2
// speedup vs baseline: 1.5203x; 1.5203x over previous
#include <cuda_runtime.h>

#define LEAK 0.2f
constexpr int B_  = 2;
constexpr int C_  = 16;
constexpr int VOL = 96 * 96 * 96;
constexpr int PLN = 96 * 96;
constexpr int DVF = 48;
constexpr int ZC  = 24;          // z-chunk per block
constexpr int NZC = 96 / ZC;     // 4

// Scratch (device globals per harness rules).
__device__ float g_warped[(size_t)B_ * C_ * VOL];  // warped src; later fsum
__device__ float g_corr[(size_t)B_ * 27 * VOL];    // cost volume
__device__ float g_facc[(size_t)B_ * C_ * VOL];    // conv1 accumulator -> f

__device__ __forceinline__ float lrelu(float v) { return v > 0.f ? v : LEAK * v; }

// ---------------------------------------------------------------------------
// K1: trilinear upsample of dvf (48^3 -> 96^3, align_corners) + warp source
// ---------------------------------------------------------------------------
__global__ void warp_kernel(const float* __restrict__ src,
                            const float* __restrict__ dvf)
{
    int idx = blockIdx.x * blockDim.x + threadIdx.x;
    if (idx >= B_ * VOL) return;
    int b = idx / VOL;
    int r = idx - b * VOL;
    int z = r / PLN;
    int y = (r / 96) % 96;
    int x = r % 96;

    const float sc = 47.0f / 95.0f;
    float pz = z * sc, py = y * sc, px = x * sc;
    int z0 = (int)pz, y0 = (int)py, x0 = (int)px;
    int z1 = min(z0 + 1, DVF - 1), y1 = min(y0 + 1, DVF - 1), x1 = min(x0 + 1, DVF - 1);
    float wz = pz - (float)z0, wy = py - (float)y0, wx = px - (float)x0;

    const float* dv = dvf + (size_t)b * 3 * DVF * DVF * DVF;
    float flow[3];
#pragma unroll
    for (int cc = 0; cc < 3; cc++) {
        const float* p = dv + (size_t)cc * DVF * DVF * DVF;
        float v000 = __ldg(p + (z0 * 48 + y0) * 48 + x0);
        float v001 = __ldg(p + (z0 * 48 + y0) * 48 + x1);
        float v010 = __ldg(p + (z0 * 48 + y1) * 48 + x0);
        float v011 = __ldg(p + (z0 * 48 + y1) * 48 + x1);
        float v100 = __ldg(p + (z1 * 48 + y0) * 48 + x0);
        float v101 = __ldg(p + (z1 * 48 + y0) * 48 + x1);
        float v110 = __ldg(p + (z1 * 48 + y1) * 48 + x0);
        float v111 = __ldg(p + (z1 * 48 + y1) * 48 + x1);
        float v00 = v000 * (1.f - wx) + v001 * wx;
        float v01 = v010 * (1.f - wx) + v011 * wx;
        float v10 = v100 * (1.f - wx) + v101 * wx;
        float v11 = v110 * (1.f - wx) + v111 * wx;
        float v0 = v00 * (1.f - wy) + v01 * wy;
        float v1 = v10 * (1.f - wy) + v11 * wy;
        flow[cc] = v0 * (1.f - wz) + v1 * wz;
    }

    float zc = (float)z + flow[0];
    float yc = (float)y + flow[1];
    float xc = (float)x + flow[2];
    float zf = floorf(zc), yf = floorf(yc), xf = floorf(xc);
    float fz = zc - zf, fy = yc - yf, fx = xc - xf;
    int iz0 = (int)zf, iy0 = (int)yf, ix0 = (int)xf;

    int   zi[2] = { iz0, iz0 + 1 };
    int   yi[2] = { iy0, iy0 + 1 };
    int   xi[2] = { ix0, ix0 + 1 };
    float wzv[2] = { 1.f - fz, fz };
    float wyv[2] = { 1.f - fy, fy };
    float wxv[2] = { 1.f - fx, fx };

    int   idx8[8];
    float w8[8];
    int j = 0;
#pragma unroll
    for (int a = 0; a < 2; a++)
#pragma unroll
        for (int bb = 0; bb < 2; bb++)
#pragma unroll
            for (int c2 = 0; c2 < 2; c2++) {
                int zz = zi[a], yy = yi[bb], xx = xi[c2];
                bool valid = (zz >= 0 && zz < 96 && yy >= 0 && yy < 96 &&
                              xx >= 0 && xx < 96);
                int zcl = min(max(zz, 0), 95);
                int ycl = min(max(yy, 0), 95);
                int xcl = min(max(xx, 0), 95);
                idx8[j] = (zcl * 96 + ycl) * 96 + xcl;
                w8[j] = valid ? (wzv[a] * wyv[bb] * wxv[c2]) : 0.f;
                j++;
            }

    const float* sb = src + (size_t)b * C_ * VOL;
    float* ob = g_warped + (size_t)b * C_ * VOL + r;
#pragma unroll
    for (int c = 0; c < C_; c++) {
        const float* sp = sb + (size_t)c * VOL;
        float v = 0.f;
#pragma unroll
        for (int k = 0; k < 8; k++) v = fmaf(w8[k], __ldg(sp + idx8[k]), v);
        ob[(size_t)c * VOL] = v;
    }
}

// ---------------------------------------------------------------------------
// K2: 27-shift cost volume
// ---------------------------------------------------------------------------
__global__ void corr_kernel(const float* __restrict__ tgt)
{
    int idx = blockIdx.x * blockDim.x + threadIdx.x;
    if (idx >= B_ * VOL) return;
    int b = idx / VOL;
    int r = idx - b * VOL;
    int z = r / PLN;
    int y = (r / 96) % 96;
    int x = r % 96;

    float t[C_];
    const float* tp = tgt + (size_t)b * C_ * VOL + r;
#pragma unroll
    for (int c = 0; c < C_; c++) t[c] = __ldg(tp + (size_t)c * VOL);

    const float* wp = g_warped + (size_t)b * C_ * VOL;
    float* op = g_corr + (size_t)b * 27 * VOL + r;

    int s = 0;
#pragma unroll
    for (int dz = -1; dz <= 1; dz++) {
        int zz = z + dz;
#pragma unroll
        for (int dy = -1; dy <= 1; dy++) {
            int yy = y + dy;
#pragma unroll
            for (int dx = -1; dx <= 1; dx++) {
                int xx = x + dx;
                float acc = 0.f;
                if (zz >= 0 && zz < 96 && yy >= 0 && yy < 96 && xx >= 0 && xx < 96) {
                    const float* q = wp + ((zz * 96 + yy) * 96 + xx);
#pragma unroll
                    for (int c = 0; c < C_; c++)
                        acc = fmaf(t[c], __ldg(q + (size_t)c * VOL), acc);
                }
                op[(size_t)s * VOL] = lrelu(acc * 0.0625f);
                s++;
            }
        }
    }
}

// ---------------------------------------------------------------------------
// Generic z-ring 3x3x3 conv pass.
// in:  [B][CIN][VOL] (uses all CIN channels of the tensor)
// w:   [COUT_TOT][CIN_TOT][27]   (ci_off selects the slice for this pass)
// Each block: x-tile 32, y-tile 4, z-chunk ZC, one COUT group of COG.
// Iterates input planes once, keeping 3 pending z-outputs in registers.
// INIT: start from bias and store; else read-modify-write accumulate.
// ACT:  apply leaky relu at the end. RES: add res[] afterwards.
// ---------------------------------------------------------------------------
template<int CIN, int CIN_TOT, int COUT_TOT, int COG, bool INIT, bool ACT, bool RES>
__global__ void __launch_bounds__(128, 5) convz_kernel(
    const float* __restrict__ in, int ci_off,
    const float* __restrict__ w, const float* __restrict__ bias,
    float* __restrict__ out, const float* __restrict__ res)
{
    constexpr int NCG = COUT_TOT / COG;
    extern __shared__ float sw[];   // [ci][tap(9)][kz(3)][co(COG)]

    int bz = blockIdx.z;
    int zc = bz % NZC;  bz /= NZC;
    int cg = bz % NCG;  bz /= NCG;
    int b  = bz;
    int co0 = cg * COG;

    int tid = threadIdx.y * 32 + threadIdx.x;
    for (int i = tid; i < CIN * 27 * COG; i += 128) {
        int co = i % COG;
        int r  = i / COG;
        int kz = r % 3; r /= 3;
        int t  = r % 9;
        int ci = r / 9;
        sw[i] = __ldg(&w[((size_t)(co0 + co) * CIN_TOT + ci_off + ci) * 27 + kz * 9 + t]);
    }
    __syncthreads();

    int x = blockIdx.x * 32 + threadIdx.x;
    int y = blockIdx.y * 4 + threadIdx.y;
    int zs = zc * ZC;

    bool vxm = (x >= 1), vxp = (x <= 94);
    bool vym = (y >= 1), vyp = (y <= 94);

    const float* ib = in + (size_t)b * CIN * VOL + y * 96 + x;
    size_t out_base = ((size_t)b * COUT_TOT + co0) * VOL + y * 96 + x;

    float bco[COG];
#pragma unroll
    for (int co = 0; co < COG; co++) bco[co] = INIT ? __ldg(bias + co0 + co) : 0.f;

    float a0[COG], a1[COG], a2[COG];
#pragma unroll
    for (int co = 0; co < COG; co++) { a0[co] = 0.f; a1[co] = 0.f; a2[co] = 0.f; }

    // At plane z: AN accumulates out z+1 (kz=0), AC out z (kz=1), AP out z-1 (kz=2).
    // After plane z: emit AP (out z-1) if in chunk, then clear AP (becomes out z+2).
#define CONV_STEP(ZP, AP, AC, AN)                                              \
    {                                                                          \
        int z = (ZP);                                                          \
        if (z >= 0 && z <= 95 && z <= zs + ZC) {                               \
            const float* pz = ib + (size_t)z * PLN;                            \
            _Pragma("unroll 1")                                                \
            for (int ci = 0; ci < CIN; ci++) {                                 \
                const float* pc = pz + (size_t)ci * VOL;                       \
                float v[9];                                                    \
                v[0] = (vym && vxm) ? __ldg(pc - 97) : 0.f;                    \
                v[1] = vym          ? __ldg(pc - 96) : 0.f;                    \
                v[2] = (vym && vxp) ? __ldg(pc - 95) : 0.f;                    \
                v[3] = vxm          ? __ldg(pc - 1)  : 0.f;                    \
                v[4] =                __ldg(pc);                               \
                v[5] = vxp          ? __ldg(pc + 1)  : 0.f;                    \
                v[6] = (vyp && vxm) ? __ldg(pc + 95) : 0.f;                    \
                v[7] = vyp          ? __ldg(pc + 96) : 0.f;                    \
                v[8] = (vyp && vxp) ? __ldg(pc + 97) : 0.f;                    \
                const float* wp = sw + ci * 27 * COG;                          \
                _Pragma("unroll")                                              \
                for (int t = 0; t < 9; t++) {                                  \
                    const float* wt = wp + t * 3 * COG;                        \
                    _Pragma("unroll")                                          \
                    for (int co = 0; co < COG; co++)                           \
                        AN[co] = fmaf(v[t], wt[co], AN[co]);                   \
                    _Pragma("unroll")                                          \
                    for (int co = 0; co < COG; co++)                           \
                        AC[co] = fmaf(v[t], wt[COG + co], AC[co]);             \
                    _Pragma("unroll")                                          \
                    for (int co = 0; co < COG; co++)                           \
                        AP[co] = fmaf(v[t], wt[2 * COG + co], AP[co]);         \
                }                                                              \
            }                                                                  \
        }                                                                      \
        int zo = z - 1;                                                        \
        if (zo >= zs && zo < zs + ZC) {                                        \
            float* po = out + out_base + (size_t)zo * PLN;                     \
            _Pragma("unroll")                                                  \
            for (int co = 0; co < COG; co++) {                                 \
                float vv;                                                      \
                if (INIT) vv = AP[co] + bco[co];                               \
                else      vv = po[(size_t)co * VOL] + AP[co];                  \
                if (ACT)  vv = lrelu(vv);                                      \
                if (RES)  vv += __ldg(res + out_base + (size_t)zo * PLN +      \
                                      (size_t)co * VOL);                       \
                po[(size_t)co * VOL] = vv;                                     \
            }                                                                  \
        }                                                                      \
        _Pragma("unroll")                                                      \
        for (int co = 0; co < COG; co++) AP[co] = 0.f;                         \
    }

    for (int zb = zs - 1; zb <= zs + ZC; zb += 3) {
        CONV_STEP(zb,     a0, a1, a2);
        CONV_STEP(zb + 1, a1, a2, a0);
        CONV_STEP(zb + 2, a2, a0, a1);
    }
#undef CONV_STEP
}

// ---------------------------------------------------------------------------
extern "C" void kernel_launch(void* const* d_in, const int* in_sizes, int n_in,
                              void* d_out, int out_size)
{
    const float* src = (const float*)d_in[0];
    const float* tgt = (const float*)d_in[1];
    const float* dvf = (const float*)d_in[2];
    const float* w1  = (const float*)d_in[3];
    const float* b1  = (const float*)d_in[4];
    const float* w2  = (const float*)d_in[5];
    const float* b2  = (const float*)d_in[6];
    const float* w3  = (const float*)d_in[7];
    const float* b3  = (const float*)d_in[8];
    float* out = (float*)d_out;

    float* warped = nullptr;
    float* corr   = nullptr;
    float* facc   = nullptr;
    cudaGetSymbolAddress((void**)&warped, g_warped);
    cudaGetSymbolAddress((void**)&corr, g_corr);
    cudaGetSymbolAddress((void**)&facc, g_facc);

    int nvox = B_ * VOL;
    warp_kernel<<<(nvox + 255) / 256, 256>>>(src, dvf);
    corr_kernel<<<(nvox + 255) / 256, 256>>>(tgt);

    dim3 blk(32, 4);
    dim3 g16(3, 24, NZC * 2 * B_);   // 2 cout-groups of 8
    dim3 g3(3, 24, NZC * 1 * B_);    // 1 cout-group of 3

    // conv1 split over CIN: source(16) init, corr(27) accumulate, target(16) accumulate+act
    convz_kernel<16, 59, 16, 8, true,  false, false>
        <<<g16, blk, 16 * 27 * 8 * sizeof(float)>>>(src,  0,  w1, b1, facc, nullptr);
    convz_kernel<27, 59, 16, 8, false, false, false>
        <<<g16, blk, 27 * 27 * 8 * sizeof(float)>>>(corr, 16, w1, b1, facc, nullptr);
    convz_kernel<16, 59, 16, 8, false, true,  false>
        <<<g16, blk, 16 * 27 * 8 * sizeof(float)>>>(tgt,  43, w1, b1, facc, nullptr);
    // conv2 + residual: fsum = f + lrelu(conv(f)); fsum stored in g_warped
    convz_kernel<16, 16, 16, 8, true,  true,  true>
        <<<g16, blk, 16 * 27 * 8 * sizeof(float)>>>(facc, 0,  w2, b2, warped, facc);
    // conv3: 16 -> 3
    convz_kernel<16, 16, 3, 3, true,  true,  false>
        <<<g3,  blk, 16 * 27 * 3 * sizeof(float)>>>(warped, 0, w3, b3, out, nullptr);
}